// round 4
// baseline (speedup 1.0000x reference)
#include <cuda_runtime.h>
#include <math.h>

// Problem constants
#define NB   4096      // batch
#define ND   1024      // feature dim
#define NH   2048      // hidden
#define NC   1000      // classes
#define NCP  1024      // padded classes
#define NT   819200    // total ragged rows
#define NF   32        // ragged feature width

// ------------------------- device scratch (no allocs allowed) -------------------------
__device__ float g_sums[NB * NF];
__device__ float g_counts[NB];
__device__ float g_means[NB * NF];
__device__ float g_combined[(size_t)NB * ND];
__device__ float g_W2p[(size_t)NCP * NH];        // fp32 W2, zero-padded rows
__device__ float g_hidf[(size_t)NB * NH];        // pre-activation
__device__ float g_hid[(size_t)NB * NH];         // post-relu hidden
__device__ float g_logits[(size_t)NB * NCP];
__device__ float g_row_lv[NB];
__device__ float g_row_sq[NB];
__device__ float g_row_ok[NB];

// ------------------------- kernels -------------------------

__global__ void zero_kernel() {
    int n = NB * NF + NB;
    for (int i = blockIdx.x * blockDim.x + threadIdx.x; i < n; i += gridDim.x * blockDim.x) {
        if (i < NB * NF) g_sums[i] = 0.f;
        else g_counts[i - NB * NF] = 0.f;
    }
}

// Segment sum over sorted ids: warp handles contiguous row range, lane = feature col.
__global__ void seg_kernel(const float* __restrict__ var, const int* __restrict__ seg) {
    int gwarp = (blockIdx.x * blockDim.x + threadIdx.x) >> 5;
    int lane  = threadIdx.x & 31;
    int nwarp = (gridDim.x * blockDim.x) >> 5;
    int per   = (NT + nwarp - 1) / nwarp;
    int r0 = gwarp * per;
    int r1 = min(NT, r0 + per);
    if (r0 >= r1) return;
    int cur = seg[r0];
    float acc = 0.f, cnt = 0.f;
    for (int r = r0; r < r1; ++r) {
        int s = seg[r];
        if (s != cur) {
            atomicAdd(&g_sums[cur * NF + lane], acc);
            if (lane == 0) atomicAdd(&g_counts[cur], cnt);
            acc = 0.f; cnt = 0.f; cur = s;
        }
        acc += var[(size_t)r * NF + lane];
        cnt += 1.f;
    }
    atomicAdd(&g_sums[cur * NF + lane], acc);
    if (lane == 0) atomicAdd(&g_counts[cur], cnt);
}

__global__ void means_kernel() {
    int i = blockIdx.x * blockDim.x + threadIdx.x;
    if (i < NB * NF) {
        int b = i >> 5;
        g_means[i] = g_sums[i] / fmaxf(g_counts[b], 1.f);
    }
}

// combined[b][d] = feature[b][d] + bv[d] + sum_f means[b][f] * Wv[d][f]
__global__ void combine_kernel(const float* __restrict__ feat, const float* __restrict__ Wv,
                               const float* __restrict__ bv) {
    __shared__ float sw[128 * 33];
    __shared__ float sm[32];
    int t = threadIdx.x;
    int d0 = blockIdx.x * 128;
    for (int i = t; i < 128 * 32; i += 128) {
        int r = i >> 5, c = i & 31;
        sw[r * 33 + c] = Wv[(size_t)(d0 + r) * NF + c];
    }
    float bvd = bv[d0 + t];
    int b0 = blockIdx.y * 64;
    for (int bb = 0; bb < 64; ++bb) {
        int b = b0 + bb;
        __syncthreads();
        if (t < 32) sm[t] = g_means[b * NF + t];
        __syncthreads();
        float acc = bvd + feat[(size_t)b * ND + d0 + t];
        #pragma unroll
        for (int f = 0; f < 32; ++f) acc += sm[f] * sw[t * 33 + f];
        g_combined[(size_t)b * ND + d0 + t] = acc;
    }
}

__global__ void pad_w2_kernel(const float* __restrict__ W2) {
    size_t n = (size_t)NCP * NH;
    for (size_t i = blockIdx.x * blockDim.x + threadIdx.x; i < n;
         i += (size_t)gridDim.x * blockDim.x) {
        int c = (int)(i / NH);
        g_W2p[i] = (c < NC) ? W2[i] : 0.f;
    }
}

// fp32 SIMT GEMM: C[M,N] = A[M,K] @ B[N,K]^T, all row-major.
// BM=BN=128, BK=16, 256 threads, 8x8 per thread.
__global__ void __launch_bounds__(256) gemm_f32(
    const float* __restrict__ A, const float* __restrict__ B, float* __restrict__ C,
    int M, int N, int K)
{
    __shared__ float As[16][132];
    __shared__ float Bs[16][132];
    const int tid = threadIdx.x;
    const int tx = tid & 15;
    const int ty = tid >> 4;
    const int row0 = blockIdx.y * 128;
    const int col0 = blockIdx.x * 128;

    float acc[8][8];
    #pragma unroll
    for (int i = 0; i < 8; i++)
        #pragma unroll
        for (int j = 0; j < 8; j++) acc[i][j] = 0.f;

    for (int k0 = 0; k0 < K; k0 += 16) {
        #pragma unroll
        for (int l = 0; l < 2; l++) {
            int idx = tid + l * 256;
            int r = idx >> 2;
            int c = (idx & 3) * 4;
            float4 va = *(const float4*)(A + (size_t)(row0 + r) * K + k0 + c);
            As[c + 0][r] = va.x; As[c + 1][r] = va.y; As[c + 2][r] = va.z; As[c + 3][r] = va.w;
            float4 vb = *(const float4*)(B + (size_t)(col0 + r) * K + k0 + c);
            Bs[c + 0][r] = vb.x; Bs[c + 1][r] = vb.y; Bs[c + 2][r] = vb.z; Bs[c + 3][r] = vb.w;
        }
        __syncthreads();
        #pragma unroll
        for (int k = 0; k < 16; k++) {
            float ar[8], br[8];
            #pragma unroll
            for (int i = 0; i < 8; i++) ar[i] = As[k][ty * 8 + i];
            #pragma unroll
            for (int j = 0; j < 8; j++) br[j] = Bs[k][tx * 8 + j];
            #pragma unroll
            for (int i = 0; i < 8; i++)
                #pragma unroll
                for (int j = 0; j < 8; j++) acc[i][j] += ar[i] * br[j];
        }
        __syncthreads();
    }
    #pragma unroll
    for (int i = 0; i < 8; i++) {
        float* crow = C + (size_t)(row0 + ty * 8 + i) * N + col0 + tx * 8;
        #pragma unroll
        for (int j = 0; j < 8; j++) crow[j] = acc[i][j];
    }
}

// g_hid = relu(g_hidf + b1)
__global__ void relu_kernel(const float* __restrict__ b1) {
    size_t n = (size_t)NB * NH;
    for (size_t i = blockIdx.x * blockDim.x + threadIdx.x; i < n;
         i += (size_t)gridDim.x * blockDim.x) {
        int h = (int)(i % NH);
        float v = g_hidf[i] + b1[h];
        g_hid[i] = v > 0.f ? v : 0.f;
    }
}

// Per-row: scalar head, log-softmax, argmax, per-row loss terms.
__global__ void __launch_bounds__(256) loss_kernel(
    const float* __restrict__ b2, const float* __restrict__ Ws,
    const float* __restrict__ bs, const int* __restrict__ tgt,
    const float* __restrict__ tsc)
{
    __shared__ float sl[NC];
    __shared__ float red[256];
    __shared__ int   redi[256];
    int b = blockIdx.x, t = threadIdx.x;

    const float* hrow = g_hid + (size_t)b * NH;
    float s = 0.f;
    for (int h = t; h < NH; h += 256) s += hrow[h] * Ws[h];
    red[t] = s; __syncthreads();
    for (int off = 128; off; off >>= 1) { if (t < off) red[t] += red[t + off]; __syncthreads(); }
    float scalar = red[0] + bs[0];
    __syncthreads();

    const float* lrow = g_logits + (size_t)b * NCP;
    float lm = -1e30f; int li = NC;
    for (int c = t; c < NC; c += 256) {
        float v = lrow[c] + b2[c];
        sl[c] = v;
        if (v > lm) { lm = v; li = c; }
    }
    red[t] = lm; redi[t] = li; __syncthreads();
    for (int off = 128; off; off >>= 1) {
        if (t < off) {
            float o = red[t + off]; int oi = redi[t + off];
            if (o > red[t] || (o == red[t] && oi < redi[t])) { red[t] = o; redi[t] = oi; }
        }
        __syncthreads();
    }
    float M = red[0]; int am = redi[0];
    __syncthreads();

    float se = 0.f;
    for (int c = t; c < NC; c += 256) se += expf(sl[c] - M);
    red[t] = se; __syncthreads();
    for (int off = 128; off; off >>= 1) { if (t < off) red[t] += red[t + off]; __syncthreads(); }

    if (t == 0) {
        float lse = M + logf(red[0]);
        int tg = tgt[b];
        g_row_lv[b] = lse - sl[tg];
        float d = scalar - tsc[b];
        g_row_sq[b] = d * d;
        g_row_ok[b] = (am == tg) ? 1.f : 0.f;
    }
}

__global__ void final_kernel(float* __restrict__ out, int out_size) {
    __shared__ float r0[256], r1[256], r2[256];
    int t = threadIdx.x;
    float a = 0.f, q = 0.f, c = 0.f;
    for (int i = t; i < NB; i += 256) { a += g_row_lv[i]; q += g_row_sq[i]; c += g_row_ok[i]; }
    r0[t] = a; r1[t] = q; r2[t] = c; __syncthreads();
    for (int off = 128; off; off >>= 1) {
        if (t < off) { r0[t] += r0[t + off]; r1[t] += r1[t + off]; r2[t] += r2[t + off]; }
        __syncthreads();
    }
    if (t == 0) {
        float lv = r0[0] / NB, ls = r1[0] / NB, ac = r2[0] / NB;
        float vals[4] = { lv + ls, lv, ls, ac };
        int n = out_size < 4 ? out_size : 4;
        for (int i = 0; i < n; i++) out[i] = vals[i];
    }
}

// ------------------------- launch -------------------------
extern "C" void kernel_launch(void* const* d_in, const int* in_sizes, int n_in,
                              void* d_out, int out_size) {
    // Resolve inputs by element count (unique except two pairs resolved by order).
    int i_feat = -1, i_var = -1, i_seg = -1, i_tv = -1, i_ts = -1, i_Wv = -1, i_bv = -1,
        i_W1 = -1, i_b1 = -1, i_W2 = -1, i_b2 = -1, i_Ws = -1, i_bs = -1;
    for (int i = 0; i < n_in; i++) {
        switch (in_sizes[i]) {
            case NB * ND:        i_feat = i; break;
            case NT * NF:        i_var  = i; break;
            case NT:             i_seg  = i; break;
            case NB:             if (i_tv < 0) i_tv = i; else i_ts = i; break;
            case ND * NF:        i_Wv   = i; break;
            case ND:             i_bv   = i; break;
            case NH * ND:        i_W1   = i; break;
            case NH:             if (i_b1 < 0) i_b1 = i; else i_Ws = i; break;
            case NC * NH:        i_W2   = i; break;
            case NC:             i_b2   = i; break;
            case 1:              i_bs   = i; break;
            default: break;
        }
    }
    if (i_feat < 0) i_feat = 0; if (i_var < 0) i_var = 1; if (i_seg < 0) i_seg = 2;
    if (i_tv < 0) i_tv = 3; if (i_ts < 0) i_ts = 4; if (i_Wv < 0) i_Wv = 5;
    if (i_bv < 0) i_bv = 6; if (i_W1 < 0) i_W1 = 7; if (i_b1 < 0) i_b1 = 8;
    if (i_W2 < 0) i_W2 = 9; if (i_b2 < 0) i_b2 = 10; if (i_Ws < 0) i_Ws = 11;
    if (i_bs < 0) i_bs = 12;

    const float* feature = (const float*)d_in[i_feat];
    const float* var_flat = (const float*)d_in[i_var];
    const int*   seg_ids  = (const int*)d_in[i_seg];
    const int*   tgt_vec  = (const int*)d_in[i_tv];
    const float* tgt_sc   = (const float*)d_in[i_ts];
    const float* Wv = (const float*)d_in[i_Wv];
    const float* bv = (const float*)d_in[i_bv];
    const float* W1 = (const float*)d_in[i_W1];
    const float* b1 = (const float*)d_in[i_b1];
    const float* W2 = (const float*)d_in[i_W2];
    const float* b2 = (const float*)d_in[i_b2];
    const float* Ws = (const float*)d_in[i_Ws];
    const float* bs = (const float*)d_in[i_bs];
    float* out = (float*)d_out;

    // CRITICAL (GB300/ATS trap): __device__ symbols passed as kernel args from
    // host code silently become HOST-shadow addresses (readable via NVLink-C2C,
    // all zeros). Resolve true device addresses via cudaGetSymbolAddress.
    // These are host-side queries, not stream ops — legal during graph capture.
    float *p_combined = 0, *p_hid = 0, *p_hidf = 0, *p_logits = 0, *p_W2p = 0;
    cudaGetSymbolAddress((void**)&p_combined, g_combined);
    cudaGetSymbolAddress((void**)&p_hidf,     g_hidf);
    cudaGetSymbolAddress((void**)&p_hid,      g_hid);
    cudaGetSymbolAddress((void**)&p_logits,   g_logits);
    cudaGetSymbolAddress((void**)&p_W2p,      g_W2p);

    zero_kernel<<<128, 256>>>();
    seg_kernel<<<592, 256>>>(var_flat, seg_ids);
    means_kernel<<<(NB * NF + 255) / 256, 256>>>();
    {
        dim3 g(ND / 128, NB / 64);
        combine_kernel<<<g, 128>>>(feature, Wv, bv);
    }
    pad_w2_kernel<<<1024, 256>>>(W2);
    {
        dim3 g(NH / 128, NB / 128);   // GEMM1: M=4096, N=2048, K=1024
        gemm_f32<<<g, 256>>>(p_combined, W1, p_hidf, NB, NH, ND);
    }
    relu_kernel<<<2048, 256>>>(b1);
    {
        dim3 g(NCP / 128, NB / 128);  // GEMM2: M=4096, N=1024(pad), K=2048
        gemm_f32<<<g, 256>>>(p_hid, p_W2p, p_logits, NB, NCP, NH);
    }
    loss_kernel<<<NB, 256>>>(b2, Ws, bs, tgt_vec, tgt_sc);
    final_kernel<<<1, 256>>>(out, out_size);
    (void)n_in;
}

// round 14
// speedup vs baseline: 3.1087x; 3.1087x over previous
#include <cuda_runtime.h>
#include <cuda_bf16.h>
#include <stdint.h>
#include <cstdint>
#include <math.h>

// Problem constants
#define NB   4096      // batch
#define ND   1024      // feature dim
#define NH   2048      // hidden
#define NC   1000      // classes
#define NCP  1024      // padded classes
#define NT   819200    // total ragged rows
#define NF   32        // ragged feature width

// ------------------------- device scratch (no allocs allowed) -------------------------
__device__ float          g_sums[NB * NF];
__device__ float          g_counts[NB];
__device__ float          g_means[NB * NF];
__device__ __nv_bfloat16  g_combined[(size_t)NB * ND];   // bf16 A for GEMM1
__device__ __nv_bfloat16  g_W1b[(size_t)NH * ND];        // bf16 W1
__device__ __nv_bfloat16  g_W2b[(size_t)NCP * NH];       // bf16 W2, zero-padded rows
__device__ float          g_hidf[(size_t)NB * NH];       // fp32 pre-activation
__device__ __nv_bfloat16  g_hidb[(size_t)NB * NH];       // bf16 post-relu hidden
__device__ float          g_logits[(size_t)NB * NCP];
__device__ float          g_row_lv[NB];
__device__ float          g_row_sq[NB];
__device__ float          g_row_ok[NB];

// ------------------------- PTX helpers -------------------------
__device__ __forceinline__ uint32_t smem_u32(const void* p) {
    return (uint32_t)__cvta_generic_to_shared(p);
}

#define LDMATRIX_X4(R0, R1, R2, R3, addr)                                          \
    asm volatile("ldmatrix.sync.aligned.m8n8.x4.shared.b16 {%0,%1,%2,%3}, [%4];"   \
                 : "=r"(R0), "=r"(R1), "=r"(R2), "=r"(R3) : "r"(addr))

#define MMA16816(D0, D1, D2, D3, A0, A1, A2, A3, B0, B1)                           \
    asm volatile("mma.sync.aligned.m16n8k16.row.col.f32.bf16.bf16.f32 "            \
                 "{%0,%1,%2,%3}, {%4,%5,%6,%7}, {%8,%9}, {%0,%1,%2,%3};"           \
                 : "+f"(D0), "+f"(D1), "+f"(D2), "+f"(D3)                          \
                 : "r"(A0), "r"(A1), "r"(A2), "r"(A3), "r"(B0), "r"(B1))

// ------------------------- kernels -------------------------

__global__ void zero_kernel() {
    int n = NB * NF + NB;
    for (int i = blockIdx.x * blockDim.x + threadIdx.x; i < n; i += gridDim.x * blockDim.x) {
        if (i < NB * NF) g_sums[i] = 0.f;
        else g_counts[i - NB * NF] = 0.f;
    }
}

// Segment sum over sorted ids: warp handles contiguous row range, lane = feature col.
__global__ void seg_kernel(const float* __restrict__ var, const int* __restrict__ seg) {
    int gwarp = (blockIdx.x * blockDim.x + threadIdx.x) >> 5;
    int lane  = threadIdx.x & 31;
    int nwarp = (gridDim.x * blockDim.x) >> 5;
    int per   = (NT + nwarp - 1) / nwarp;
    int r0 = gwarp * per;
    int r1 = min(NT, r0 + per);
    if (r0 >= r1) return;
    int cur = seg[r0];
    float acc = 0.f, cnt = 0.f;
    for (int r = r0; r < r1; ++r) {
        int s = seg[r];
        if (s != cur) {
            atomicAdd(&g_sums[cur * NF + lane], acc);
            if (lane == 0) atomicAdd(&g_counts[cur], cnt);
            acc = 0.f; cnt = 0.f; cur = s;
        }
        acc += var[(size_t)r * NF + lane];
        cnt += 1.f;
    }
    atomicAdd(&g_sums[cur * NF + lane], acc);
    if (lane == 0) atomicAdd(&g_counts[cur], cnt);
}

__global__ void means_kernel() {
    int i = blockIdx.x * blockDim.x + threadIdx.x;
    if (i < NB * NF) {
        int b = i >> 5;
        g_means[i] = g_sums[i] / fmaxf(g_counts[b], 1.f);
    }
}

// combined[b][d] = bf16(feature[b][d] + bv[d] + sum_f means[b][f] * Wv[d][f])
// (round-4-passing structure; only the store type changed to bf16)
__global__ void combine_kernel(const float* __restrict__ feat, const float* __restrict__ Wv,
                               const float* __restrict__ bv) {
    __shared__ float sw[128 * 33];
    __shared__ float sm[32];
    int t = threadIdx.x;
    int d0 = blockIdx.x * 128;
    for (int i = t; i < 128 * 32; i += 128) {
        int r = i >> 5, c = i & 31;
        sw[r * 33 + c] = Wv[(size_t)(d0 + r) * NF + c];
    }
    float bvd = bv[d0 + t];
    int b0 = blockIdx.y * 64;
    for (int bb = 0; bb < 64; ++bb) {
        int b = b0 + bb;
        __syncthreads();
        if (t < 32) sm[t] = g_means[b * NF + t];
        __syncthreads();
        float acc = bvd + feat[(size_t)b * ND + d0 + t];
        #pragma unroll
        for (int f = 0; f < 32; ++f) acc += sm[f] * sw[t * 33 + f];
        g_combined[(size_t)b * ND + d0 + t] = __float2bfloat16(acc);
    }
}

__global__ void conv_w1_kernel(const float* __restrict__ W1) {
    size_t n = (size_t)NH * ND;
    for (size_t i = blockIdx.x * blockDim.x + threadIdx.x; i < n;
         i += (size_t)gridDim.x * blockDim.x)
        g_W1b[i] = __float2bfloat16(W1[i]);
}

__global__ void conv_w2_kernel(const float* __restrict__ W2) {
    size_t n = (size_t)NCP * NH;
    for (size_t i = blockIdx.x * blockDim.x + threadIdx.x; i < n;
         i += (size_t)gridDim.x * blockDim.x) {
        int c = (int)(i / NH);
        g_W2b[i] = (c < NC) ? __float2bfloat16(W2[i]) : __float2bfloat16(0.f);
    }
}

// bf16 tensor-core GEMM via explicit PTX mma.m16n8k16 + ldmatrix.
// C[M,N] = A[M,K] @ B[N,K]^T, fp32 accumulate.
// Block 128x128, BK=32, double-buffered smem, 8 warps (2 m x 4 n), warp tile 64x32.
#define BM 128
#define BN 128
#define BK 32
__global__ void __launch_bounds__(256) gemm_bf16(
    const __nv_bfloat16* __restrict__ A, const __nv_bfloat16* __restrict__ B,
    float* __restrict__ C, int M, int N, int K)
{
    __shared__ __align__(16) __nv_bfloat16 As[2][BM][40];  // row stride 80B: 16B-aligned rows,
    __shared__ __align__(16) __nv_bfloat16 Bs[2][BN][40];  // LDSM phases conflict-free
    const int tid  = threadIdx.x;
    const int lane = tid & 31;
    const int warp = tid >> 5;
    const int wm = warp >> 2;        // 0..1 -> m offset wm*64
    const int wn = warp & 3;         // 0..3 -> n offset wn*32
    const int row0 = blockIdx.y * BM;
    const int col0 = blockIdx.x * BN;

    // accumulators: d[mi][nj][4]  (mi: 4 x m16, nj: 4 x n8)
    float d[4][4][4];
    #pragma unroll
    for (int i = 0; i < 4; i++)
        #pragma unroll
        for (int j = 0; j < 4; j++)
            #pragma unroll
            for (int r = 0; r < 4; r++) d[i][j][r] = 0.f;

    // gmem -> smem copy mapping (int4 = 8 bf16 per thread, 2 row-halves)
    const int lr = tid >> 2;          // 0..63
    const int lc = (tid & 3) * 8;     // 0,8,16,24
    const size_t aBase = (size_t)(row0 + lr) * K + lc;
    const size_t bBase = (size_t)(col0 + lr) * K + lc;

    // ldmatrix per-lane source coordinates (PTX ISA m16n8k16 fragment maps)
    // A x4: lanes 0-7 -> (m 0-7, k0) = a0 ; 8-15 -> (m 8-15, k0) = a1
    //       16-23 -> (m 0-7, k8) = a2 ; 24-31 -> (m 8-15, k8) = a3
    const int a_m = ((lane >> 3) & 1) * 8 + (lane & 7);
    const int a_k = (lane >> 4) * 8;
    // B x4 (covers two n8 tiles): lanes 0-7 -> (n 0-7, k0) ; 8-15 -> (n 0-7, k8)
    //       16-23 -> (n 8-15, k0) ; 24-31 -> (n 8-15, k8)
    const int b_n = (lane >> 4) * 8 + (lane & 7);
    const int b_k = ((lane >> 3) & 1) * 8;

    // stage 0
    #pragma unroll
    for (int h = 0; h < 2; h++) {
        *(int4*)&As[0][lr + h * 64][lc] = *(const int4*)(A + aBase + (size_t)h * 64 * K);
        *(int4*)&Bs[0][lr + h * 64][lc] = *(const int4*)(B + bBase + (size_t)h * 64 * K);
    }
    __syncthreads();

    const int nk = K / BK;
    for (int it = 0; it < nk; ++it) {
        int cur = it & 1;
        if (it + 1 < nk) {
            int k0 = (it + 1) * BK;
            #pragma unroll
            for (int h = 0; h < 2; h++) {
                *(int4*)&As[cur ^ 1][lr + h * 64][lc] =
                    *(const int4*)(A + aBase + (size_t)h * 64 * K + k0);
                *(int4*)&Bs[cur ^ 1][lr + h * 64][lc] =
                    *(const int4*)(B + bBase + (size_t)h * 64 * K + k0);
            }
        }
        #pragma unroll
        for (int ks = 0; ks < BK; ks += 16) {
            uint32_t af[4][4];
            #pragma unroll
            for (int i = 0; i < 4; i++) {
                uint32_t addr = smem_u32(&As[cur][wm * 64 + i * 16 + a_m][ks + a_k]);
                LDMATRIX_X4(af[i][0], af[i][1], af[i][2], af[i][3], addr);
            }
            uint32_t bf[2][4];
            #pragma unroll
            for (int p = 0; p < 2; p++) {
                uint32_t addr = smem_u32(&Bs[cur][wn * 32 + p * 16 + b_n][ks + b_k]);
                LDMATRIX_X4(bf[p][0], bf[p][1], bf[p][2], bf[p][3], addr);
            }
            #pragma unroll
            for (int i = 0; i < 4; i++)
                #pragma unroll
                for (int j = 0; j < 4; j++) {
                    int p = j >> 1, q = (j & 1) * 2;
                    MMA16816(d[i][j][0], d[i][j][1], d[i][j][2], d[i][j][3],
                             af[i][0], af[i][1], af[i][2], af[i][3],
                             bf[p][q], bf[p][q + 1]);
                }
        }
        __syncthreads();
    }

    // epilogue: d0=(g,2t) d1=(g,2t+1) d2=(g+8,2t) d3=(g+8,2t+1)
    const int g  = lane >> 2;
    const int tg = lane & 3;
    #pragma unroll
    for (int i = 0; i < 4; i++)
        #pragma unroll
        for (int j = 0; j < 4; j++) {
            int r = row0 + wm * 64 + i * 16 + g;
            int c = col0 + wn * 32 + j * 8 + tg * 2;
            float2 v01 = make_float2(d[i][j][0], d[i][j][1]);
            float2 v23 = make_float2(d[i][j][2], d[i][j][3]);
            *(float2*)(C + (size_t)r * N + c) = v01;
            *(float2*)(C + (size_t)(r + 8) * N + c) = v23;
        }
}

// g_hidb = bf16(relu(g_hidf + b1))
__global__ void relu_kernel(const float* __restrict__ b1) {
    size_t n = (size_t)NB * NH;
    for (size_t i = blockIdx.x * blockDim.x + threadIdx.x; i < n;
         i += (size_t)gridDim.x * blockDim.x) {
        int h = (int)(i % NH);
        float v = g_hidf[i] + b1[h];
        g_hidb[i] = __float2bfloat16(v > 0.f ? v : 0.f);
    }
}

// Per-row: scalar head, log-softmax, argmax, per-row loss terms.
__global__ void __launch_bounds__(256) loss_kernel(
    const float* __restrict__ b2, const float* __restrict__ Ws,
    const float* __restrict__ bs, const int* __restrict__ tgt,
    const float* __restrict__ tsc)
{
    __shared__ float sl[NC];
    __shared__ float red[256];
    __shared__ int   redi[256];
    int b = blockIdx.x, t = threadIdx.x;

    const __nv_bfloat16* hrow = g_hidb + (size_t)b * NH;
    float s = 0.f;
    for (int h = t; h < NH; h += 256) s += __bfloat162float(hrow[h]) * Ws[h];
    red[t] = s; __syncthreads();
    for (int off = 128; off; off >>= 1) { if (t < off) red[t] += red[t + off]; __syncthreads(); }
    float scalar = red[0] + bs[0];
    __syncthreads();

    const float* lrow = g_logits + (size_t)b * NCP;
    float lm = -1e30f; int li = NC;
    for (int c = t; c < NC; c += 256) {
        float v = lrow[c] + b2[c];
        sl[c] = v;
        if (v > lm) { lm = v; li = c; }
    }
    red[t] = lm; redi[t] = li; __syncthreads();
    for (int off = 128; off; off >>= 1) {
        if (t < off) {
            float o = red[t + off]; int oi = redi[t + off];
            if (o > red[t] || (o == red[t] && oi < redi[t])) { red[t] = o; redi[t] = oi; }
        }
        __syncthreads();
    }
    float M = red[0]; int am = redi[0];
    __syncthreads();

    float se = 0.f;
    for (int c = t; c < NC; c += 256) se += expf(sl[c] - M);
    red[t] = se; __syncthreads();
    for (int off = 128; off; off >>= 1) { if (t < off) red[t] += red[t + off]; __syncthreads(); }

    if (t == 0) {
        float lse = M + logf(red[0]);
        int tg = tgt[b];
        g_row_lv[b] = lse - sl[tg];
        float dd = scalar - tsc[b];
        g_row_sq[b] = dd * dd;
        g_row_ok[b] = (am == tg) ? 1.f : 0.f;
    }
}

__global__ void final_kernel(float* __restrict__ out, int out_size) {
    __shared__ float r0[256], r1[256], r2[256];
    int t = threadIdx.x;
    float a = 0.f, q = 0.f, c = 0.f;
    for (int i = t; i < NB; i += 256) { a += g_row_lv[i]; q += g_row_sq[i]; c += g_row_ok[i]; }
    r0[t] = a; r1[t] = q; r2[t] = c; __syncthreads();
    for (int off = 128; off; off >>= 1) {
        if (t < off) { r0[t] += r0[t + off]; r1[t] += r1[t + off]; r2[t] += r2[t + off]; }
        __syncthreads();
    }
    if (t == 0) {
        float lv = r0[0] / NB, ls = r1[0] / NB, ac = r2[0] / NB;
        float vals[4] = { lv + ls, lv, ls, ac };
        int n = out_size < 4 ? out_size : 4;
        for (int i = 0; i < n; i++) out[i] = vals[i];
    }
}

// ------------------------- launch -------------------------
extern "C" void kernel_launch(void* const* d_in, const int* in_sizes, int n_in,
                              void* d_out, int out_size) {
    // Resolve inputs by element count (unique except two pairs resolved by order).
    int i_feat = -1, i_var = -1, i_seg = -1, i_tv = -1, i_ts = -1, i_Wv = -1, i_bv = -1,
        i_W1 = -1, i_b1 = -1, i_W2 = -1, i_b2 = -1, i_Ws = -1, i_bs = -1;
    for (int i = 0; i < n_in; i++) {
        switch (in_sizes[i]) {
            case NB * ND:        i_feat = i; break;
            case NT * NF:        i_var  = i; break;
            case NT:             i_seg  = i; break;
            case NB:             if (i_tv < 0) i_tv = i; else i_ts = i; break;
            case ND * NF:        i_Wv   = i; break;
            case ND:             i_bv   = i; break;
            case NH * ND:        i_W1   = i; break;
            case NH:             if (i_b1 < 0) i_b1 = i; else i_Ws = i; break;
            case NC * NH:        i_W2   = i; break;
            case NC:             i_b2   = i; break;
            case 1:              i_bs   = i; break;
            default: break;
        }
    }
    if (i_feat < 0) i_feat = 0; if (i_var < 0) i_var = 1; if (i_seg < 0) i_seg = 2;
    if (i_tv < 0) i_tv = 3; if (i_ts < 0) i_ts = 4; if (i_Wv < 0) i_Wv = 5;
    if (i_bv < 0) i_bv = 6; if (i_W1 < 0) i_W1 = 7; if (i_b1 < 0) i_b1 = 8;
    if (i_W2 < 0) i_W2 = 9; if (i_b2 < 0) i_b2 = 10; if (i_Ws < 0) i_Ws = 11;
    if (i_bs < 0) i_bs = 12;

    const float* feature = (const float*)d_in[i_feat];
    const float* var_flat = (const float*)d_in[i_var];
    const int*   seg_ids  = (const int*)d_in[i_seg];
    const int*   tgt_vec  = (const int*)d_in[i_tv];
    const float* tgt_sc   = (const float*)d_in[i_ts];
    const float* Wv = (const float*)d_in[i_Wv];
    const float* bv = (const float*)d_in[i_bv];
    const float* W1 = (const float*)d_in[i_W1];
    const float* b1 = (const float*)d_in[i_b1];
    const float* W2 = (const float*)d_in[i_W2];
    const float* b2 = (const float*)d_in[i_b2];
    const float* Ws = (const float*)d_in[i_Ws];
    const float* bs = (const float*)d_in[i_bs];
    float* out = (float*)d_out;

    // GB300/ATS trap: __device__ symbols passed as kernel args from host become
    // host-shadow addresses. Resolve true device addresses explicitly.
    __nv_bfloat16 *p_combined = 0, *p_W1b = 0, *p_W2b = 0, *p_hidb = 0;
    float *p_hidf = 0, *p_logits = 0;
    cudaGetSymbolAddress((void**)&p_combined, g_combined);
    cudaGetSymbolAddress((void**)&p_W1b,      g_W1b);
    cudaGetSymbolAddress((void**)&p_W2b,      g_W2b);
    cudaGetSymbolAddress((void**)&p_hidb,     g_hidb);
    cudaGetSymbolAddress((void**)&p_hidf,     g_hidf);
    cudaGetSymbolAddress((void**)&p_logits,   g_logits);

    zero_kernel<<<128, 256>>>();
    seg_kernel<<<592, 256>>>(var_flat, seg_ids);
    means_kernel<<<(NB * NF + 255) / 256, 256>>>();
    {
        dim3 g(ND / 128, NB / 64);
        combine_kernel<<<g, 128>>>(feature, Wv, bv);
    }
    conv_w1_kernel<<<1024, 256>>>(W1);
    conv_w2_kernel<<<1024, 256>>>(W2);
    {
        dim3 g(NH / BN, NB / BM);     // GEMM1: M=4096, N=2048, K=1024
        gemm_bf16<<<g, 256>>>(p_combined, p_W1b, p_hidf, NB, NH, ND);
    }
    relu_kernel<<<2048, 256>>>(b1);
    {
        dim3 g(NCP / BN, NB / BM);    // GEMM2: M=4096, N=1024(pad), K=2048
        gemm_bf16<<<g, 256>>>(p_hidb, p_W2b, p_logits, NB, NCP, NH);
    }
    loss_kernel<<<NB, 256>>>(b2, Ws, bs, tgt_vec, tgt_sc);
    final_kernel<<<1, 256>>>(out, out_size);
    (void)n_in;
}

// round 17
// speedup vs baseline: 4.3179x; 1.3890x over previous
#include <cuda_runtime.h>
#include <cuda_bf16.h>
#include <stdint.h>
#include <cstdint>
#include <math.h>

// Problem constants
#define NB   4096      // batch
#define ND   1024      // feature dim
#define NH   2048      // hidden
#define NC   1000      // classes
#define NCP  1024      // padded classes
#define NT   819200    // total ragged rows
#define NF   32        // ragged feature width

// ------------------------- device scratch (no allocs allowed) -------------------------
__device__ float          g_sums[NB * NF];
__device__ float          g_counts[NB];
__device__ __nv_bfloat16  g_combined[(size_t)NB * ND];   // bf16 A for GEMM1
__device__ __nv_bfloat16  g_W1b[(size_t)NH * ND];        // bf16 W1
__device__ __nv_bfloat16  g_W2b[(size_t)NCP * NH];       // bf16 W2, zero-padded rows
__device__ __nv_bfloat16  g_hidb[(size_t)NB * NH];       // bf16 post-relu hidden
__device__ float          g_logits[(size_t)NB * NCP];
__device__ float          g_row_lv[NB];
__device__ float          g_row_sq[NB];
__device__ float          g_row_ok[NB];

// ------------------------- PTX helpers -------------------------
__device__ __forceinline__ uint32_t smem_u32(const void* p) {
    return (uint32_t)__cvta_generic_to_shared(p);
}

#define LDMATRIX_X4(R0, R1, R2, R3, addr)                                          \
    asm volatile("ldmatrix.sync.aligned.m8n8.x4.shared.b16 {%0,%1,%2,%3}, [%4];"   \
                 : "=r"(R0), "=r"(R1), "=r"(R2), "=r"(R3) : "r"(addr))

#define MMA16816(D0, D1, D2, D3, A0, A1, A2, A3, B0, B1)                           \
    asm volatile("mma.sync.aligned.m16n8k16.row.col.f32.bf16.bf16.f32 "            \
                 "{%0,%1,%2,%3}, {%4,%5,%6,%7}, {%8,%9}, {%0,%1,%2,%3};"           \
                 : "+f"(D0), "+f"(D1), "+f"(D2), "+f"(D3)                          \
                 : "r"(A0), "r"(A1), "r"(A2), "r"(A3), "r"(B0), "r"(B1))

#define CP_ASYNC16(dst_u32, src_ptr)                                               \
    asm volatile("cp.async.cg.shared.global [%0], [%1], 16;"                       \
                 :: "r"(dst_u32), "l"(src_ptr) : "memory")
#define CP_COMMIT()  asm volatile("cp.async.commit_group;" ::: "memory")
#define CP_WAIT1()   asm volatile("cp.async.wait_group 1;" ::: "memory")

// ------------------------- kernels -------------------------

__global__ void zero_kernel() {
    int n = NB * NF + NB;
    for (int i = blockIdx.x * blockDim.x + threadIdx.x; i < n; i += gridDim.x * blockDim.x) {
        if (i < NB * NF) g_sums[i] = 0.f;
        else g_counts[i - NB * NF] = 0.f;
    }
}

// Segment sum over sorted ids: warp handles contiguous row range, lane = feature col.
__global__ void seg_kernel(const float* __restrict__ var, const int* __restrict__ seg) {
    int gwarp = (blockIdx.x * blockDim.x + threadIdx.x) >> 5;
    int lane  = threadIdx.x & 31;
    int nwarp = (gridDim.x * blockDim.x) >> 5;
    int per   = (NT + nwarp - 1) / nwarp;
    int r0 = gwarp * per;
    int r1 = min(NT, r0 + per);
    if (r0 >= r1) return;
    int cur = seg[r0];
    float acc = 0.f, cnt = 0.f;
    for (int r = r0; r < r1; ++r) {
        int s = seg[r];
        if (s != cur) {
            atomicAdd(&g_sums[cur * NF + lane], acc);
            if (lane == 0) atomicAdd(&g_counts[cur], cnt);
            acc = 0.f; cnt = 0.f; cur = s;
        }
        acc += var[(size_t)r * NF + lane];
        cnt += 1.f;
    }
    atomicAdd(&g_sums[cur * NF + lane], acc);
    if (lane == 0) atomicAdd(&g_counts[cur], cnt);
}

// combined[b][d] = bf16(feature[b][d] + bv[d] + sum_f mean[b][f] * Wv[d][f])
// block 256 threads = 256 d-cols; 32 batch rows per block; ONE barrier.
// Means computed in-place from sums/counts (means_kernel folded in).
__global__ void __launch_bounds__(256) combine_kernel(
    const float* __restrict__ feat, const float* __restrict__ Wv,
    const float* __restrict__ bv)
{
    __shared__ float sw[256 * 33];   // Wv chunk [256 d][32 f], pad 33
    __shared__ float sm[32 * 33];    // 32 means rows, pad 33
    int t = threadIdx.x;
    int d0 = blockIdx.x * 256;
    int b0 = blockIdx.y * 32;
    #pragma unroll
    for (int i = t; i < 256 * 32; i += 256) {
        int r = i >> 5, c = i & 31;
        sw[r * 33 + c] = Wv[(size_t)(d0 + r) * NF + c];
    }
    #pragma unroll
    for (int i = t; i < 32 * 32; i += 256) {
        int r = i >> 5, c = i & 31;
        sm[r * 33 + c] = g_sums[(b0 + r) * NF + c] / fmaxf(g_counts[b0 + r], 1.f);
    }
    __syncthreads();
    float bvd = bv[d0 + t];
    const float* swt = sw + t * 33;
    #pragma unroll 4
    for (int bb = 0; bb < 32; ++bb) {
        int b = b0 + bb;
        const float* m = sm + bb * 33;
        float acc = bvd + feat[(size_t)b * ND + d0 + t];
        #pragma unroll
        for (int f = 0; f < 32; ++f) acc += m[f] * swt[f];
        g_combined[(size_t)b * ND + d0 + t] = __float2bfloat16(acc);
    }
}

__global__ void conv_w1_kernel(const float* __restrict__ W1) {
    size_t n = (size_t)NH * ND;
    for (size_t i = blockIdx.x * blockDim.x + threadIdx.x; i < n;
         i += (size_t)gridDim.x * blockDim.x)
        g_W1b[i] = __float2bfloat16(W1[i]);
}

__global__ void conv_w2_kernel(const float* __restrict__ W2) {
    size_t n = (size_t)NCP * NH;
    for (size_t i = blockIdx.x * blockDim.x + threadIdx.x; i < n;
         i += (size_t)gridDim.x * blockDim.x) {
        int c = (int)(i / NH);
        g_W2b[i] = (c < NC) ? __float2bfloat16(W2[i]) : __float2bfloat16(0.f);
    }
}

// bf16 tensor-core GEMM via PTX mma.m16n8k16 + ldmatrix, cp.async 3-stage pipeline.
// C[M,N] = A[M,K] @ B[N,K]^T, fp32 accumulate.
// EPI=0: store fp32 to C.  EPI=1: store bf16(relu(acc + bias[n])) to Cb.
#define BM 128
#define BN 128
#define BK 32
template<int EPI>
__global__ void __launch_bounds__(256) gemm_bf16(
    const __nv_bfloat16* __restrict__ A, const __nv_bfloat16* __restrict__ B,
    float* __restrict__ C, __nv_bfloat16* __restrict__ Cb,
    const float* __restrict__ bias, int M, int N, int K)
{
    __shared__ __align__(16) __nv_bfloat16 As[3][BM][40];  // row stride 80B (16B-aligned)
    __shared__ __align__(16) __nv_bfloat16 Bs[3][BN][40];
    const int tid  = threadIdx.x;
    const int lane = tid & 31;
    const int warp = tid >> 5;
    const int wm = warp >> 2;        // 0..1 -> m offset wm*64
    const int wn = warp & 3;         // 0..3 -> n offset wn*32
    const int row0 = blockIdx.y * BM;
    const int col0 = blockIdx.x * BN;

    float d[4][4][4];
    #pragma unroll
    for (int i = 0; i < 4; i++)
        #pragma unroll
        for (int j = 0; j < 4; j++)
            #pragma unroll
            for (int r = 0; r < 4; r++) d[i][j][r] = 0.f;

    // gmem -> smem copy mapping (16B = 8 bf16 per thread, 2 row-halves each array)
    const int lr = tid >> 2;          // 0..63
    const int lc = (tid & 3) * 8;     // 0,8,16,24
    const size_t aBase = (size_t)(row0 + lr) * K + lc;
    const size_t bBase = (size_t)(col0 + lr) * K + lc;

    // ldmatrix per-lane source coordinates (PTX ISA m16n8k16 fragment maps)
    const int a_m = ((lane >> 3) & 1) * 8 + (lane & 7);
    const int a_k = (lane >> 4) * 8;
    const int b_n = (lane >> 4) * 8 + (lane & 7);
    const int b_k = ((lane >> 3) & 1) * 8;

    const int nk = K / BK;

    // prefetch stages 0,1
    #pragma unroll
    for (int s = 0; s < 2; s++) {
        int k0 = s * BK;
        #pragma unroll
        for (int h = 0; h < 2; h++) {
            CP_ASYNC16(smem_u32(&As[s][lr + h * 64][lc]), A + aBase + (size_t)h * 64 * K + k0);
            CP_ASYNC16(smem_u32(&Bs[s][lr + h * 64][lc]), B + bBase + (size_t)h * 64 * K + k0);
        }
        CP_COMMIT();
    }

    for (int it = 0; it < nk; ++it) {
        const int st = it % 3;
        CP_WAIT1();
        __syncthreads();
        #pragma unroll
        for (int ks = 0; ks < BK; ks += 16) {
            uint32_t af[4][4];
            #pragma unroll
            for (int i = 0; i < 4; i++) {
                uint32_t addr = smem_u32(&As[st][wm * 64 + i * 16 + a_m][ks + a_k]);
                LDMATRIX_X4(af[i][0], af[i][1], af[i][2], af[i][3], addr);
            }
            uint32_t bf[2][4];
            #pragma unroll
            for (int p = 0; p < 2; p++) {
                uint32_t addr = smem_u32(&Bs[st][wn * 32 + p * 16 + b_n][ks + b_k]);
                LDMATRIX_X4(bf[p][0], bf[p][1], bf[p][2], bf[p][3], addr);
            }
            #pragma unroll
            for (int i = 0; i < 4; i++)
                #pragma unroll
                for (int j = 0; j < 4; j++) {
                    int p = j >> 1, q = (j & 1) * 2;
                    MMA16816(d[i][j][0], d[i][j][1], d[i][j][2], d[i][j][3],
                             af[i][0], af[i][1], af[i][2], af[i][3],
                             bf[p][q], bf[p][q + 1]);
                }
        }
        // issue loads for stage it+2 (safe: stage (it+2)%3 compute finished before
        // this iteration's barrier); empty commit keeps wait_group bookkeeping exact.
        if (it + 2 < nk) {
            int ps = (it + 2) % 3;
            int k0 = (it + 2) * BK;
            #pragma unroll
            for (int h = 0; h < 2; h++) {
                CP_ASYNC16(smem_u32(&As[ps][lr + h * 64][lc]), A + aBase + (size_t)h * 64 * K + k0);
                CP_ASYNC16(smem_u32(&Bs[ps][lr + h * 64][lc]), B + bBase + (size_t)h * 64 * K + k0);
            }
            CP_COMMIT();
        } else {
            CP_COMMIT();
        }
    }

    // epilogue: d0=(g,2t) d1=(g,2t+1) d2=(g+8,2t) d3=(g+8,2t+1)
    const int g  = lane >> 2;
    const int tg = lane & 3;
    #pragma unroll
    for (int i = 0; i < 4; i++)
        #pragma unroll
        for (int j = 0; j < 4; j++) {
            int r = row0 + wm * 64 + i * 16 + g;
            int c = col0 + wn * 32 + j * 8 + tg * 2;
            if (EPI == 0) {
                *(float2*)(C + (size_t)r * N + c)       = make_float2(d[i][j][0], d[i][j][1]);
                *(float2*)(C + (size_t)(r + 8) * N + c) = make_float2(d[i][j][2], d[i][j][3]);
            } else {
                float bc0 = bias[c], bc1 = bias[c + 1];
                float v0 = d[i][j][0] + bc0, v1 = d[i][j][1] + bc1;
                float v2 = d[i][j][2] + bc0, v3 = d[i][j][3] + bc1;
                v0 = v0 > 0.f ? v0 : 0.f;  v1 = v1 > 0.f ? v1 : 0.f;
                v2 = v2 > 0.f ? v2 : 0.f;  v3 = v3 > 0.f ? v3 : 0.f;
                *(__nv_bfloat162*)(Cb + (size_t)r * N + c)       = __floats2bfloat162_rn(v0, v1);
                *(__nv_bfloat162*)(Cb + (size_t)(r + 8) * N + c) = __floats2bfloat162_rn(v2, v3);
            }
        }
}

// Per-row: scalar head, log-softmax, argmax, per-row loss terms.
__global__ void __launch_bounds__(256) loss_kernel(
    const float* __restrict__ b2, const float* __restrict__ Ws,
    const float* __restrict__ bs, const int* __restrict__ tgt,
    const float* __restrict__ tsc)
{
    __shared__ float sl[NC];
    __shared__ float red[256];
    __shared__ int   redi[256];
    int b = blockIdx.x, t = threadIdx.x;

    const __nv_bfloat16* hrow = g_hidb + (size_t)b * NH;
    float s = 0.f;
    for (int h = t; h < NH; h += 256) s += __bfloat162float(hrow[h]) * Ws[h];
    red[t] = s; __syncthreads();
    for (int off = 128; off; off >>= 1) { if (t < off) red[t] += red[t + off]; __syncthreads(); }
    float scalar = red[0] + bs[0];
    __syncthreads();

    const float* lrow = g_logits + (size_t)b * NCP;
    float lm = -1e30f; int li = NC;
    for (int c = t; c < NC; c += 256) {
        float v = lrow[c] + b2[c];
        sl[c] = v;
        if (v > lm) { lm = v; li = c; }
    }
    red[t] = lm; redi[t] = li; __syncthreads();
    for (int off = 128; off; off >>= 1) {
        if (t < off) {
            float o = red[t + off]; int oi = redi[t + off];
            if (o > red[t] || (o == red[t] && oi < redi[t])) { red[t] = o; redi[t] = oi; }
        }
        __syncthreads();
    }
    float M = red[0]; int am = redi[0];
    __syncthreads();

    float se = 0.f;
    for (int c = t; c < NC; c += 256) se += expf(sl[c] - M);
    red[t] = se; __syncthreads();
    for (int off = 128; off; off >>= 1) { if (t < off) red[t] += red[t + off]; __syncthreads(); }

    if (t == 0) {
        float lse = M + logf(red[0]);
        int tg = tgt[b];
        g_row_lv[b] = lse - sl[tg];
        float dd = scalar - tsc[b];
        g_row_sq[b] = dd * dd;
        g_row_ok[b] = (am == tg) ? 1.f : 0.f;
    }
}

__global__ void final_kernel(float* __restrict__ out, int out_size) {
    __shared__ float r0[256], r1[256], r2[256];
    int t = threadIdx.x;
    float a = 0.f, q = 0.f, c = 0.f;
    for (int i = t; i < NB; i += 256) { a += g_row_lv[i]; q += g_row_sq[i]; c += g_row_ok[i]; }
    r0[t] = a; r1[t] = q; r2[t] = c; __syncthreads();
    for (int off = 128; off; off >>= 1) {
        if (t < off) { r0[t] += r0[t + off]; r1[t] += r1[t + off]; r2[t] += r2[t + off]; }
        __syncthreads();
    }
    if (t == 0) {
        float lv = r0[0] / NB, ls = r1[0] / NB, ac = r2[0] / NB;
        float vals[4] = { lv + ls, lv, ls, ac };
        int n = out_size < 4 ? out_size : 4;
        for (int i = 0; i < n; i++) out[i] = vals[i];
    }
}

// ------------------------- launch -------------------------
extern "C" void kernel_launch(void* const* d_in, const int* in_sizes, int n_in,
                              void* d_out, int out_size) {
    // Resolve inputs by element count (unique except two pairs resolved by order).
    int i_feat = -1, i_var = -1, i_seg = -1, i_tv = -1, i_ts = -1, i_Wv = -1, i_bv = -1,
        i_W1 = -1, i_b1 = -1, i_W2 = -1, i_b2 = -1, i_Ws = -1, i_bs = -1;
    for (int i = 0; i < n_in; i++) {
        switch (in_sizes[i]) {
            case NB * ND:        i_feat = i; break;
            case NT * NF:        i_var  = i; break;
            case NT:             i_seg  = i; break;
            case NB:             if (i_tv < 0) i_tv = i; else i_ts = i; break;
            case ND * NF:        i_Wv   = i; break;
            case ND:             i_bv   = i; break;
            case NH * ND:        i_W1   = i; break;
            case NH:             if (i_b1 < 0) i_b1 = i; else i_Ws = i; break;
            case NC * NH:        i_W2   = i; break;
            case NC:             i_b2   = i; break;
            case 1:              i_bs   = i; break;
            default: break;
        }
    }
    if (i_feat < 0) i_feat = 0; if (i_var < 0) i_var = 1; if (i_seg < 0) i_seg = 2;
    if (i_tv < 0) i_tv = 3; if (i_ts < 0) i_ts = 4; if (i_Wv < 0) i_Wv = 5;
    if (i_bv < 0) i_bv = 6; if (i_W1 < 0) i_W1 = 7; if (i_b1 < 0) i_b1 = 8;
    if (i_W2 < 0) i_W2 = 9; if (i_b2 < 0) i_b2 = 10; if (i_Ws < 0) i_Ws = 11;
    if (i_bs < 0) i_bs = 12;

    const float* feature = (const float*)d_in[i_feat];
    const float* var_flat = (const float*)d_in[i_var];
    const int*   seg_ids  = (const int*)d_in[i_seg];
    const int*   tgt_vec  = (const int*)d_in[i_tv];
    const float* tgt_sc   = (const float*)d_in[i_ts];
    const float* Wv = (const float*)d_in[i_Wv];
    const float* bv = (const float*)d_in[i_bv];
    const float* W1 = (const float*)d_in[i_W1];
    const float* b1 = (const float*)d_in[i_b1];
    const float* W2 = (const float*)d_in[i_W2];
    const float* b2 = (const float*)d_in[i_b2];
    const float* Ws = (const float*)d_in[i_Ws];
    const float* bs = (const float*)d_in[i_bs];
    float* out = (float*)d_out;

    // GB300/ATS trap: __device__ symbols passed as kernel args from host become
    // host-shadow addresses. Resolve true device addresses explicitly.
    __nv_bfloat16 *p_combined = 0, *p_W1b = 0, *p_W2b = 0, *p_hidb = 0;
    float *p_logits = 0;
    cudaGetSymbolAddress((void**)&p_combined, g_combined);
    cudaGetSymbolAddress((void**)&p_W1b,      g_W1b);
    cudaGetSymbolAddress((void**)&p_W2b,      g_W2b);
    cudaGetSymbolAddress((void**)&p_hidb,     g_hidb);
    cudaGetSymbolAddress((void**)&p_logits,   g_logits);

    zero_kernel<<<128, 256>>>();
    seg_kernel<<<592, 256>>>(var_flat, seg_ids);
    {
        dim3 g(ND / 256, NB / 32);
        combine_kernel<<<g, 256>>>(feature, Wv, bv);
    }
    conv_w1_kernel<<<1024, 256>>>(W1);
    conv_w2_kernel<<<1024, 256>>>(W2);
    {
        dim3 g(NH / BN, NB / BM);     // GEMM1: M=4096, N=2048, K=1024, fused bias+relu+bf16
        gemm_bf16<1><<<g, 256>>>(p_combined, p_W1b, (float*)0, p_hidb, b1, NB, NH, ND);
    }
    {
        dim3 g(NCP / BN, NB / BM);    // GEMM2: M=4096, N=1024(pad), K=2048
        gemm_bf16<0><<<g, 256>>>(p_hidb, p_W2b, p_logits, (__nv_bfloat16*)0, (const float*)0, NB, NCP, NH);
    }
    loss_kernel<<<NB, 256>>>(b2, Ws, bs, tgt_vec, tgt_sc);
    final_kernel<<<1, 256>>>(out, out_size);
    (void)n_in;
}